// round 15
// baseline (speedup 1.0000x reference)
#include <cuda_runtime.h>
#include <cuda_fp16.h>

// Problem dims (fixed by reference)
#define UDIM 400
#define VDIM 400
#define MDIM 4
#define NTEX (MDIM * UDIM * VDIM)          // 640,000 records

// j-pair fp16 table: per texel (m,i,j) one 64B record (32 halves):
//   halves [ 0..11] = texel (i, j):   W00..W22 row-major, B0,B1,B2
//   halves [12..15] = pad
//   halves [16..27] = texel (i, j+1 mod 400)  (j-wrap baked in)
//   halves [28..31] = pad
// 64B-aligned -> a lane pair's two 32B halves ALWAYS share one 128B line.
__device__ __align__(64) unsigned g_tbl[(size_t)NTEX * 16];

__global__ __launch_bounds__(256) void pack_kernel(
    const float* __restrict__ m_param,
    const float* __restrict__ b_param)
{
    int t = blockIdx.x * blockDim.x + threadIdx.x;
    if (t >= NTEX) return;
    int j  = t % VDIM;
    int j2 = j + 1; if (j2 == VDIM) j2 = 0;
    size_t src1 = (size_t)t;                    // (m,i,j) linear
    size_t src2 = (size_t)(t - j + j2);         // (m,i,j2) linear

    __align__(64) __half h[32];
    {
        const float* w = m_param + src1 * 9;
        const float* b = b_param + src1 * 3;
        #pragma unroll
        for (int k = 0; k < 9; k++) h[k] = __float2half_rn(w[k]);
        #pragma unroll
        for (int k = 0; k < 3; k++) h[9 + k] = __float2half_rn(b[k]);
        h[12] = h[13] = h[14] = h[15] = __half(0.0f);
    }
    {
        const float* w = m_param + src2 * 9;
        const float* b = b_param + src2 * 3;
        #pragma unroll
        for (int k = 0; k < 9; k++) h[16 + k] = __float2half_rn(w[k]);
        #pragma unroll
        for (int k = 0; k < 3; k++) h[25 + k] = __float2half_rn(b[k]);
        h[28] = h[29] = h[30] = h[31] = __half(0.0f);
    }

    const uint4* s = reinterpret_cast<const uint4*>(h);
    uint4* dst = reinterpret_cast<uint4*>(g_tbl + (size_t)t * 16);
    dst[0] = s[0]; dst[1] = s[1]; dst[2] = s[2]; dst[3] = s[3];
}

__device__ __forceinline__ void ldg256(const void* p, unsigned r[8]) {
    asm("ld.global.nc.v8.b32 {%0,%1,%2,%3,%4,%5,%6,%7}, [%8];"
        : "=r"(r[0]), "=r"(r[1]), "=r"(r[2]), "=r"(r[3]),
          "=r"(r[4]), "=r"(r[5]), "=r"(r[6]), "=r"(r[7])
        : "l"(p));
}

// Per-point setup: table byte offsets of the two i-rows + fractions.
__device__ __forceinline__ void point_setup(float uu, float vv, int mm,
                                            unsigned& offA, unsigned& offB,
                                            float& ir, float& jr) {
    float iu = uu * (float)UDIM;
    float iv = vv * (float)VDIM;
    if (iu == (float)UDIM) iu = (float)(UDIM - 1);
    if (iv == (float)VDIM) iv = (float)(VDIM - 1);

    float i1f = floorf(iu);
    float j1f = floorf(iv);
    int i1 = (int)i1f;
    int j1 = (int)j1f;                        // j+1 half lives inside the record
    int i2 = i1 + 1; if (i2 == UDIM) i2 = 0;  // i wraps
    ir = iu - i1f;
    jr = iv - j1f;

    offA = (unsigned)((mm * UDIM + i1) * VDIM + j1) * 64u;
    offB = (unsigned)((mm * UDIM + i2) * VDIM + j1) * 64u;
}

// fp16 i-blend + fp32 matvec + j-weight. Record half2 slots s=0..5:
// [0]=(W00,W01) [1]=(W02,W10) [2]=(W11,W12) [3]=(W20,W21) [4]=(W22,B0) [5]=(B1,B2)
__device__ __forceinline__ void point_math(const unsigned recA[8], const unsigned recB[8],
                                           float ir, float jw,
                                           float x0, float x1, float x2,
                                           float& o0, float& o1, float& o2) {
    __half2 irh = __float2half2_rn(ir);
    float2 c[6];
    #pragma unroll
    for (int s = 0; s < 6; s++) {
        __half2 ha = *reinterpret_cast<const __half2*>(&recA[s]);
        __half2 hb = *reinterpret_cast<const __half2*>(&recB[s]);
        __half2 f = __hfma2(irh, __hsub2(hb, ha), ha);
        c[s] = __half22float2(f);
    }
    o0 = fmaf(x0, c[0].x, fmaf(x1, c[1].y, fmaf(x2, c[3].x, c[4].y))) * jw;
    o1 = fmaf(x0, c[0].y, fmaf(x1, c[2].x, fmaf(x2, c[3].y, c[5].x))) * jw;
    o2 = fmaf(x0, c[1].x, fmaf(x1, c[2].y, fmaf(x2, c[4].x, c[5].y))) * jw;
}

// Lane-pair cooperative interp, 2 points per thread (32 points per warp).
//   lane even -> j-half (offset +0),  weight (1-jr)
//   lane odd  -> j+1-half (offset +32), weight jr
// All 4 LDG.256 issued up front for MLP; pair halves always share a 128B line.
__global__ __launch_bounds__(256) void interp_kernel(
    const float* __restrict__ x,
    const int*   __restrict__ m,
    const float* __restrict__ u,
    const float* __restrict__ v,
    float* __restrict__ out,
    int N)
{
    int tid  = blockIdx.x * blockDim.x + threadIdx.x;
    int gw   = tid >> 5;                 // global warp index
    int lane = tid & 31;
    int pair = lane >> 1;                // 0..15
    int odd  = lane & 1;

    long long base_pt = (long long)gw * 32;
    long long P0 = base_pt + pair;
    long long P1 = base_pt + 16 + pair;
    bool v0 = (P0 < (long long)N);
    bool v1 = (P1 < (long long)N);
    if (!v0) return;                     // whole warp's points beyond N only at tail warp
    int t0 = (int)P0;
    int t1 = v1 ? (int)P1 : t0;          // clamp: keep lanes active for shfl

    // --- setup (both lanes of a pair compute identically; loads merge) ---
    unsigned offA0, offB0, offA1, offB1;
    float ir0, jr0, ir1, jr1;
    point_setup(u[t0], v[t0], m[t0], offA0, offB0, ir0, jr0);
    point_setup(u[t1], v[t1], m[t1], offA1, offB1, ir1, jr1);

    unsigned jo = odd ? 32u : 0u;
    const char* base = reinterpret_cast<const char*>(g_tbl);

    // --- all 4 table loads up front (MLP=4) ---
    unsigned recA0[8], recB0[8], recA1[8], recB1[8];
    ldg256(base + offA0 + jo, recA0);
    ldg256(base + offB0 + jo, recB0);
    ldg256(base + offA1 + jo, recA1);
    ldg256(base + offB1 + jo, recB1);

    float x00 = x[3 * t0 + 0], x01 = x[3 * t0 + 1], x02 = x[3 * t0 + 2];
    float x10 = x[3 * t1 + 0], x11 = x[3 * t1 + 1], x12 = x[3 * t1 + 2];

    // --- point 0 ---
    float jw0 = odd ? jr0 : (1.0f - jr0);
    float o00, o01, o02;
    point_math(recA0, recB0, ir0, jw0, x00, x01, x02, o00, o01, o02);
    o00 += __shfl_xor_sync(0xffffffffu, o00, 1);
    o01 += __shfl_xor_sync(0xffffffffu, o01, 1);
    o02 += __shfl_xor_sync(0xffffffffu, o02, 1);
    if (!odd) {
        out[3 * t0 + 0] = o00;
        out[3 * t0 + 1] = o01;
        out[3 * t0 + 2] = o02;
    }

    // --- point 1 ---
    float jw1 = odd ? jr1 : (1.0f - jr1);
    float o10, o11, o12;
    point_math(recA1, recB1, ir1, jw1, x10, x11, x12, o10, o11, o12);
    o10 += __shfl_xor_sync(0xffffffffu, o10, 1);
    o11 += __shfl_xor_sync(0xffffffffu, o11, 1);
    o12 += __shfl_xor_sync(0xffffffffu, o12, 1);
    if (v1 && !odd) {
        out[3 * t1 + 0] = o10;
        out[3 * t1 + 1] = o11;
        out[3 * t1 + 2] = o12;
    }
}

extern "C" void kernel_launch(void* const* d_in, const int* in_sizes, int n_in,
                              void* d_out, int out_size) {
    const float* x       = (const float*)d_in[0];   // [N,3]
    const int*   m       = (const int*)  d_in[1];   // [N]
    const float* u       = (const float*)d_in[2];   // [N]
    const float* v       = (const float*)d_in[3];   // [N]
    const float* m_param = (const float*)d_in[4];   // [M,U*V,3,3]
    const float* b_param = (const float*)d_in[5];   // [M,U*V,1,3]
    float* out = (float*)d_out;

    int N = in_sizes[1];  // element count of m

    // Stage 1: build 64B j-pair fp16 records (41 MB), single streaming pass
    {
        int blocks = (NTEX + 255) / 256;
        pack_kernel<<<blocks, 256>>>(m_param, b_param);
    }
    // Stage 2: lane-pair cooperative gather, 2 points/thread (32 points/warp)
    {
        long long warps = ((long long)N + 31) / 32;
        long long threads_total = warps * 32;
        int blocks = (int)((threads_total + 255) / 256);
        interp_kernel<<<blocks, 256>>>(x, m, u, v, out, N);
    }
}

// round 17
// speedup vs baseline: 1.2005x; 1.2005x over previous
#include <cuda_runtime.h>
#include <cuda_fp16.h>

typedef unsigned long long u64;

// Problem dims (fixed by reference)
#define UDIM 400
#define VDIM 400
#define MDIM 4
#define NTEX (MDIM * UDIM * VDIM)          // 640,000 records

// j-pair fp16 table: per texel (m,i,j) one 64B record (32 halves):
//   halves [ 0..11] = texel (i, j):   W00..W22 row-major, B0,B1,B2
//   halves [12..15] = pad
//   halves [16..27] = texel (i, j+1 mod 400)  (j-wrap baked in)
//   halves [28..31] = pad
// 64B-aligned -> a lane pair's two 32B halves ALWAYS share one 128B line.
__device__ __align__(64) unsigned g_tbl[(size_t)NTEX * 16];

// ---------------- policy + hinted access helpers ----------------
__device__ __forceinline__ u64 pol_evict_last() {
    u64 p; asm("createpolicy.fractional.L2::evict_last.b64 %0, 1.0;" : "=l"(p)); return p;
}
__device__ __forceinline__ u64 pol_evict_first() {
    u64 p; asm("createpolicy.fractional.L2::evict_first.b64 %0, 1.0;" : "=l"(p)); return p;
}
__device__ __forceinline__ void ldg256_hint(const void* p, u64 pol, unsigned r[8]) {
    asm("ld.global.nc.L2::cache_hint.v8.b32 {%0,%1,%2,%3,%4,%5,%6,%7}, [%8], %9;"
        : "=r"(r[0]), "=r"(r[1]), "=r"(r[2]), "=r"(r[3]),
          "=r"(r[4]), "=r"(r[5]), "=r"(r[6]), "=r"(r[7])
        : "l"(p), "l"(pol));
}
__device__ __forceinline__ float ldf_hint(const float* p, u64 pol) {
    float v; asm("ld.global.L2::cache_hint.f32 %0, [%1], %2;" : "=f"(v) : "l"(p), "l"(pol));
    return v;
}
__device__ __forceinline__ int ldi_hint(const int* p, u64 pol) {
    int v; asm("ld.global.L2::cache_hint.b32 %0, [%1], %2;" : "=r"(v) : "l"(p), "l"(pol));
    return v;
}
__device__ __forceinline__ void stf_hint(float* p, float v, u64 pol) {
    asm("st.global.L2::cache_hint.f32 [%0], %1, %2;" :: "l"(p), "f"(v), "l"(pol) : "memory");
}

// ---------------- pack: single streaming pass ----------------
__global__ __launch_bounds__(256) void pack_kernel(
    const float* __restrict__ m_param,
    const float* __restrict__ b_param)
{
    int t = blockIdx.x * blockDim.x + threadIdx.x;
    if (t >= NTEX) return;
    int j  = t % VDIM;
    int j2 = j + 1; if (j2 == VDIM) j2 = 0;
    size_t src1 = (size_t)t;                    // (m,i,j) linear
    size_t src2 = (size_t)(t - j + j2);         // (m,i,j2) linear

    __align__(64) __half h[32];
    {
        const float* w = m_param + src1 * 9;
        const float* b = b_param + src1 * 3;
        #pragma unroll
        for (int k = 0; k < 9; k++) h[k] = __float2half_rn(w[k]);
        #pragma unroll
        for (int k = 0; k < 3; k++) h[9 + k] = __float2half_rn(b[k]);
        h[12] = h[13] = h[14] = h[15] = __half(0.0f);
    }
    {
        const float* w = m_param + src2 * 9;
        const float* b = b_param + src2 * 3;
        #pragma unroll
        for (int k = 0; k < 9; k++) h[16 + k] = __float2half_rn(w[k]);
        #pragma unroll
        for (int k = 0; k < 3; k++) h[25 + k] = __float2half_rn(b[k]);
        h[28] = h[29] = h[30] = h[31] = __half(0.0f);
    }

    const uint4* s = reinterpret_cast<const uint4*>(h);
    uint4* dst = reinterpret_cast<uint4*>(g_tbl + (size_t)t * 16);
    dst[0] = s[0]; dst[1] = s[1]; dst[2] = s[2]; dst[3] = s[3];
}

// Lane-pair cooperative interp: 2 lanes per point (R14 structure).
//   lane even -> j-half (offset +0),  weight (1-jr)
//   lane odd  -> j+1-half (offset +32), weight jr
// Table loads hinted evict_last; streams hinted evict_first.
__global__ __launch_bounds__(256) void interp_kernel(
    const float* __restrict__ x,
    const int*   __restrict__ m,
    const float* __restrict__ u,
    const float* __restrict__ v,
    float* __restrict__ out,
    int N)
{
    int tid  = blockIdx.x * blockDim.x + threadIdx.x;
    int gw   = tid >> 5;                 // global warp index
    int lane = tid & 31;
    int pair = lane >> 1;                // 0..15: point slot within warp
    int odd  = lane & 1;

    long long P = (long long)gw * 16 + pair;
    bool valid = (P < (long long)N);
    int t = valid ? (int)P : (N - 1);    // clamp: all lanes stay active for shfl

    u64 pl = pol_evict_last();
    u64 pf = pol_evict_first();

    // --- setup (both lanes of a pair compute identically; loads merge) ---
    float iu = ldf_hint(u + t, pf) * (float)UDIM;
    float iv = ldf_hint(v + t, pf) * (float)VDIM;
    if (iu == (float)UDIM) iu = (float)(UDIM - 1);
    if (iv == (float)VDIM) iv = (float)(VDIM - 1);

    float i1f = floorf(iu);
    float j1f = floorf(iv);
    int i1 = (int)i1f;
    int j1 = (int)j1f;                        // j+1 half lives inside the record
    int i2 = i1 + 1; if (i2 == UDIM) i2 = 0;  // i wraps
    float ir = iu - i1f;
    float jr = iv - j1f;

    int mm = ldi_hint(m + t, pf);
    unsigned offA = (unsigned)((mm * UDIM + i1) * VDIM + j1) * 64u;
    unsigned offB = (unsigned)((mm * UDIM + i2) * VDIM + j1) * 64u;
    unsigned jo = odd ? 32u : 0u;             // odd lane takes the j+1 half

    // --- cooperative gather: 2 LDG.256 per lane; pair always shares the line ---
    const char* base = reinterpret_cast<const char*>(g_tbl);
    unsigned recA[8], recB[8];
    ldg256_hint(base + offA + jo, pl, recA);  // (i1, j1+odd)
    ldg256_hint(base + offB + jo, pl, recB);  // (i2, j1+odd)

    float x0 = ldf_hint(x + 3 * t + 0, pf);
    float x1 = ldf_hint(x + 3 * t + 1, pf);
    float x2 = ldf_hint(x + 3 * t + 2, pf);

    // --- i-blend in fp32; record half2 slots s=0..5:
    // [0]=(W00,W01) [1]=(W02,W10) [2]=(W11,W12) [3]=(W20,W21) [4]=(W22,B0) [5]=(B1,B2)
    float2 acc[6];
    #pragma unroll
    for (int s = 0; s < 6; s++) {
        float2 fa = __half22float2(*reinterpret_cast<const __half2*>(&recA[s]));
        float2 fb = __half22float2(*reinterpret_cast<const __half2*>(&recB[s]));
        acc[s].x = fmaf(ir, fb.x - fa.x, fa.x);
        acc[s].y = fmaf(ir, fb.y - fa.y, fa.y);
    }

    // partial matvec: y_lane = x . W_lane + B_lane, then scale by j-weight
    float jw = odd ? jr : (1.0f - jr);
    float o0 = fmaf(x0, acc[0].x, fmaf(x1, acc[1].y, fmaf(x2, acc[3].x, acc[4].y))) * jw;
    float o1 = fmaf(x0, acc[0].y, fmaf(x1, acc[2].x, fmaf(x2, acc[3].y, acc[5].x))) * jw;
    float o2 = fmaf(x0, acc[1].x, fmaf(x1, acc[2].y, fmaf(x2, acc[4].x, acc[5].y))) * jw;

    // combine the lane pair
    o0 += __shfl_xor_sync(0xffffffffu, o0, 1);
    o1 += __shfl_xor_sync(0xffffffffu, o1, 1);
    o2 += __shfl_xor_sync(0xffffffffu, o2, 1);

    // even lane stores all three floats (scalar, always aligned)
    if (valid && !odd) {
        stf_hint(out + 3 * t + 0, o0, pf);
        stf_hint(out + 3 * t + 1, o1, pf);
        stf_hint(out + 3 * t + 2, o2, pf);
    }
}

extern "C" void kernel_launch(void* const* d_in, const int* in_sizes, int n_in,
                              void* d_out, int out_size) {
    const float* x       = (const float*)d_in[0];   // [N,3]
    const int*   m       = (const int*)  d_in[1];   // [N]
    const float* u       = (const float*)d_in[2];   // [N]
    const float* v       = (const float*)d_in[3];   // [N]
    const float* m_param = (const float*)d_in[4];   // [M,U*V,3,3]
    const float* b_param = (const float*)d_in[5];   // [M,U*V,1,3]
    float* out = (float*)d_out;

    int N = in_sizes[1];  // element count of m

    // Stage 1: build 64B j-pair fp16 records (41 MB), single streaming pass
    {
        int blocks = (NTEX + 255) / 256;
        pack_kernel<<<blocks, 256>>>(m_param, b_param);
    }
    // Stage 2: lane-pair cooperative gather + blend + matvec (16 points/warp)
    {
        long long warps = ((long long)N + 15) / 16;
        long long threads_total = warps * 32;
        int blocks = (int)((threads_total + 255) / 256);
        interp_kernel<<<blocks, 256>>>(x, m, u, v, out, N);
    }
}